// round 9
// baseline (speedup 1.0000x reference)
#include <cuda_runtime.h>

// rosa_emb_layer: B=8, T=2048, V=50257, C=768
// inputs: d_in[0] = idx (B,T) int32, d_in[1] = emb (V,C) float32
// output: (B,T,C) float32
//
// R9: decisive write-roofline experiment. Every previous shape (STG v4/v8,
// TMA bulk, early/late stores, smem vs L1 compares) clamps output writes at
// ~4.2 TB/s with no named SOL ceiling hit. K1 is the fastest conceivable
// writer of the 50MB output: zero logic, zero loads, 12 independent
// st.global.v8 per thread, fully coalesced. K2 = R1's proven match kernel
// (smem compare scan, (L<<11)|j packed max == argmax(L+j*1e-5)), epilogue
// reduced to overwriting the ~42 matched rows with emb data (stream order
// puts it after K1's zeros).

#define TT 2048
#define BB 8
#define CC 768
#define WPB 8

#define ZCTAS 512
#define ZTHR  256
#define ZPER  12   // v8 stores per thread: 512*256*12*8 = 12,582,912 floats

__device__ __forceinline__ void stg_v8_zero(float* p) {
    asm volatile("st.global.v8.f32 [%0], {%1,%1,%1,%1,%1,%1,%1,%1};"
                 :: "l"(p), "f"(0.0f) : "memory");
}

__device__ __forceinline__ void stg_v8(float* p, const float* r) {
    asm volatile("st.global.v8.f32 [%0], {%1,%2,%3,%4,%5,%6,%7,%8};"
                 :: "l"(p), "f"(r[0]), "f"(r[1]), "f"(r[2]), "f"(r[3]),
                    "f"(r[4]), "f"(r[5]), "f"(r[6]), "f"(r[7]) : "memory");
}

__device__ __forceinline__ void ldg_v8(const float* p, float* r) {
    asm volatile("ld.global.nc.v8.f32 {%0,%1,%2,%3,%4,%5,%6,%7}, [%8];"
                 : "=f"(r[0]), "=f"(r[1]), "=f"(r[2]), "=f"(r[3]),
                   "=f"(r[4]), "=f"(r[5]), "=f"(r[6]), "=f"(r[7])
                 : "l"(p));
}

// K1: pure zero-fill, maximum store MLP, no dependencies at all.
__global__ __launch_bounds__(ZTHR)
void zero_kernel(float* __restrict__ out) {
    const size_t t = (size_t)blockIdx.x * ZTHR + threadIdx.x;
    float* p = out + t * 8;
    const size_t stride = (size_t)ZCTAS * ZTHR * 8;   // octet stride
    #pragma unroll
    for (int k = 0; k < ZPER; k++)
        stg_v8_zero(p + k * stride);
}

// K2: R1 match kernel; writes ONLY matched rows (zeros already laid down).
__global__ __launch_bounds__(256, 8)
void rosa_match_fix_kernel(const int* __restrict__ idx,
                           const float* __restrict__ emb,
                           float* __restrict__ out) {
    __shared__ int xs[TT];

    const int cta_per_b = TT / WPB;               // 256
    const int b      = blockIdx.x / cta_per_b;
    const int i_base = (blockIdx.x % cta_per_b) * WPB;
    const int tid  = threadIdx.x;
    const int w    = tid >> 5;
    const int lane = tid & 31;

    const int4* g  = (const int4*)(idx + (size_t)b * TT);
    int4*       s4 = (int4*)xs;
    #pragma unroll
    for (int k = tid; k < TT / 4; k += 256) s4[k] = g[k];
    __syncthreads();

    const int i  = i_base + w;
    const int xi = xs[i];

    int best = 0;   // (L<<11)|j ; 0 == no match
    for (int j0 = lane * 4; j0 < i; j0 += 128) {
        const int4 v = s4[j0 >> 2];
        const bool m0 = (v.x == xi);
        const bool m1 = (v.y == xi) & (j0 + 1 < i);
        const bool m2 = (v.z == xi) & (j0 + 2 < i);
        const bool m3 = (v.w == xi) & (j0 + 3 < i);
        if (m0 | m1 | m2 | m3) {
            #pragma unroll
            for (int c = 0; c < 4; c++) {
                const bool m = (c == 0) ? m0 : (c == 1) ? m1 : (c == 2) ? m2 : m3;
                if (m) {
                    const int j = j0 + c;
                    int L = 1, t = 1;
                    while (t <= j && xs[i - t] == xs[j - t]) { ++L; ++t; }
                    const int packed = (L << 11) | j;
                    if (packed > best) best = packed;
                }
            }
        }
    }

    #pragma unroll
    for (int o = 16; o; o >>= 1)
        best = max(best, __shfl_xor_sync(0xffffffffu, best, o));

    if (best >= (1 << 11)) {   // rare: ~42 rows in the whole problem
        const int bj = best & 2047;
        int pidx = bj + 1; if (pidx > TT - 1) pidx = TT - 1;
        const int tok = xs[pidx];
        const float* erow = emb + (size_t)tok * CC;
        float* orow = out + ((size_t)b * TT + i) * CC;
        float r[24];
        #pragma unroll
        for (int k = 0; k < 3; k++)
            ldg_v8(erow + (lane + 32 * k) * 8, r + 8 * k);
        #pragma unroll
        for (int k = 0; k < 3; k++)
            stg_v8(orow + (lane + 32 * k) * 8, r + 8 * k);
    }
}

extern "C" void kernel_launch(void* const* d_in, const int* in_sizes, int n_in,
                              void* d_out, int out_size) {
    const int*   idx = (const int*)d_in[0];
    const float* emb = (const float*)d_in[1];
    float*       out = (float*)d_out;

    zero_kernel<<<ZCTAS, ZTHR>>>(out);
    rosa_match_fix_kernel<<<BB * (TT / WPB), 256>>>(idx, emb, out);
}

// round 10
// speedup vs baseline: 1.1045x; 1.1045x over previous
#include <cuda_runtime.h>

// rosa_emb_layer: B=8, T=2048, V=50257, C=768
// inputs: d_in[0] = idx (B,T) int32, d_in[1] = emb (V,C) float32
// output: (B,T,C) float32
//
// R10: R9's split proved (a) match phase alone = 9us (latency-bound: 16K
// warps, 14 CTA waves, serial LDS chains), (b) pure store floor = ~9us.
// So: 4 rows per warp (4x LDS amortization, 4x fewer warps/fills/trips),
// 512 CTAs resident in ONE wave, bounds-mask-free fast path, fused with
// phase-0 optimistic zero stores so the ~9us store drain hides the ~2-3us
// compute. Rare matched rows (~42 total) overwritten at the end by the
// same lanes (per-thread same-address store order).
// (L<<11)|j integer max == argmax(L + j*1e-5) with larger-j tie-break.

#define TT 2048
#define BB 8
#define CC 768
#define RPW 4                 // rows per warp
#define WPB 8                 // warps per CTA
#define RPC (RPW * WPB)       // rows per CTA = 32
#define CPB (TT / RPC)        // CTAs per batch = 64

__device__ __forceinline__ void stg_v8_zero(float* p) {
    asm volatile("st.global.v8.f32 [%0], {%1,%1,%1,%1,%1,%1,%1,%1};"
                 :: "l"(p), "f"(0.0f) : "memory");
}

__device__ __forceinline__ void stg_v8(float* p, const float* r) {
    asm volatile("st.global.v8.f32 [%0], {%1,%2,%3,%4,%5,%6,%7,%8};"
                 :: "l"(p), "f"(r[0]), "f"(r[1]), "f"(r[2]), "f"(r[3]),
                    "f"(r[4]), "f"(r[5]), "f"(r[6]), "f"(r[7]) : "memory");
}

__device__ __forceinline__ void ldg_v8(const float* p, float* r) {
    asm volatile("ld.global.nc.v8.f32 {%0,%1,%2,%3,%4,%5,%6,%7}, [%8];"
                 : "=f"(r[0]), "=f"(r[1]), "=f"(r[2]), "=f"(r[3]),
                   "=f"(r[4]), "=f"(r[5]), "=f"(r[6]), "=f"(r[7])
                 : "l"(p));
}

__global__ __launch_bounds__(256, 6)
void rosa_fused_kernel(const int* __restrict__ idx,
                       const float* __restrict__ emb,
                       float* __restrict__ out) {
    __shared__ int xs[TT];

    const int b    = blockIdx.x >> 6;            // / CPB
    const int rb   = (blockIdx.x & (CPB - 1)) * RPC;
    const int tid  = threadIdx.x;
    const int w    = tid >> 5;
    const int lane = tid & 31;
    const int i0   = rb + RPW * w;               // first of this warp's 4 rows

    // ---- Phase 0: optimistic zero stores for all 4 rows (no deps). ----
    float* obase = out + ((size_t)b * TT + i0) * CC;
    #pragma unroll
    for (int r = 0; r < RPW; r++)
        #pragma unroll
        for (int k = 0; k < 3; k++)
            stg_v8_zero(obase + (size_t)r * CC + (lane + 32 * k) * 8);

    // ---- Phase 1: fill smem token row (8 KB). ----
    const int4* g  = (const int4*)(idx + (size_t)b * TT);
    int4*       s4 = (int4*)xs;
    s4[tid]       = g[tid];
    s4[tid + 256] = g[tid + 256];
    __syncthreads();

    int xi[RPW], best[RPW];
    #pragma unroll
    for (int r = 0; r < RPW; r++) { xi[r] = xs[i0 + r]; best[r] = 0; }

    // ---- Phase 2a: full trips — whole 128-chunk < i0, no bounds masks. ----
    int base = 0;
    for (; base + 128 <= i0; base += 128) {
        const int j0 = base + lane * 4;
        const int4 v = s4[j0 >> 2];
        #pragma unroll
        for (int r = 0; r < RPW; r++) {
            const int x = xi[r];
            if ((v.x == x) | (v.y == x) | (v.z == x) | (v.w == x)) {  // rare
                #pragma unroll
                for (int c = 0; c < 4; c++) {
                    const int e = (c == 0) ? v.x : (c == 1) ? v.y : (c == 2) ? v.z : v.w;
                    if (e == x) {
                        const int j = j0 + c, i = i0 + r;
                        int L = 1, t = 1;
                        while (t <= j && xs[i - t] == xs[j - t]) { ++L; ++t; }
                        const int p = (L << 11) | j;
                        if (p > best[r]) best[r] = p;
                    }
                }
            }
        }
    }

    // ---- Phase 2b: tail trips — per-row j < i_r masks. ----
    const int jend = i0 + RPW - 1;   // strict upper bound on any needed j+1
    for (; base < jend; base += 128) {
        const int j0 = base + lane * 4;
        if (j0 < jend) {
            const int4 v = s4[j0 >> 2];
            #pragma unroll
            for (int r = 0; r < RPW; r++) {
                const int x  = xi[r];
                const int ir = i0 + r;
                const bool m0 = (v.x == x) & (j0     < ir);
                const bool m1 = (v.y == x) & (j0 + 1 < ir);
                const bool m2 = (v.z == x) & (j0 + 2 < ir);
                const bool m3 = (v.w == x) & (j0 + 3 < ir);
                if (m0 | m1 | m2 | m3) {
                    #pragma unroll
                    for (int c = 0; c < 4; c++) {
                        const bool m = (c == 0) ? m0 : (c == 1) ? m1 : (c == 2) ? m2 : m3;
                        if (m) {
                            const int j = j0 + c;
                            int L = 1, t = 1;
                            while (t <= j && xs[ir - t] == xs[j - t]) { ++L; ++t; }
                            const int p = (L << 11) | j;
                            if (p > best[r]) best[r] = p;
                        }
                    }
                }
            }
        }
    }

    // ---- Phase 3: per-row warp reduce + rare emb fix-up overwrite. ----
    #pragma unroll
    for (int r = 0; r < RPW; r++) {
        int bst = best[r];
        #pragma unroll
        for (int o = 16; o; o >>= 1)
            bst = max(bst, __shfl_xor_sync(0xffffffffu, bst, o));
        if (bst >= (1 << 11)) {                  // matched row (rare)
            int pidx = (bst & 2047) + 1;
            if (pidx > TT - 1) pidx = TT - 1;
            const int tok = xs[pidx];
            const float* erow = emb + (size_t)tok * CC;
            float* orow = obase + (size_t)r * CC;
            float rv[24];
            #pragma unroll
            for (int k = 0; k < 3; k++)
                ldg_v8(erow + (lane + 32 * k) * 8, rv + 8 * k);
            #pragma unroll
            for (int k = 0; k < 3; k++)
                stg_v8(orow + (lane + 32 * k) * 8, rv + 8 * k);
        }
    }
}

extern "C" void kernel_launch(void* const* d_in, const int* in_sizes, int n_in,
                              void* d_out, int out_size) {
    const int*   idx = (const int*)d_in[0];
    const float* emb = (const float*)d_in[1];
    float*       out = (float*)d_out;

    rosa_fused_kernel<<<BB * CPB, 256>>>(idx, emb, out);
}

// round 11
// speedup vs baseline: 1.2786x; 1.1577x over previous
#include <cuda_runtime.h>

// rosa_emb_layer: B=8, T=2048, V=50257, C=768
// inputs: d_in[0] = idx (B,T) int32, d_in[1] = emb (V,C) float32
// output: (B,T,C) float32
//
// R11: 2 strided rows per warp (i, i+1024). Measured components: match
// latency-bound at 9.06us (2.4 CTA waves), store floor 9.9us (5.1 TB/s L2
// write acceptance). This shape: 1024 CTAs (~1.2 waves, occ ~86%), each
// LDS.128 feeds both rows' compares (33% less smem traffic), every warp has
// identical trip count (perfect balance), full chunks skip bounds masks.
// Zero stores fire right after the smem fill so the ~9.9us drain overlaps
// the whole compare phase. Matched rows (~42 total) overwritten at the end
// (same lanes, same addresses -> per-thread store order).
// (L<<11)|j integer max == argmax(L + j*1e-5) with larger-j tie-break.

#define TT 2048
#define BB 8
#define CC 768

__device__ __forceinline__ void stg_v8_zero(float* p) {
    asm volatile("st.global.v8.f32 [%0], {%1,%1,%1,%1,%1,%1,%1,%1};"
                 :: "l"(p), "f"(0.0f) : "memory");
}

__device__ __forceinline__ void stg_v8(float* p, const float* r) {
    asm volatile("st.global.v8.f32 [%0], {%1,%2,%3,%4,%5,%6,%7,%8};"
                 :: "l"(p), "f"(r[0]), "f"(r[1]), "f"(r[2]), "f"(r[3]),
                    "f"(r[4]), "f"(r[5]), "f"(r[6]), "f"(r[7]) : "memory");
}

__device__ __forceinline__ void ldg_v8(const float* p, float* r) {
    asm volatile("ld.global.nc.v8.f32 {%0,%1,%2,%3,%4,%5,%6,%7}, [%8];"
                 : "=f"(r[0]), "=f"(r[1]), "=f"(r[2]), "=f"(r[3]),
                   "=f"(r[4]), "=f"(r[5]), "=f"(r[6]), "=f"(r[7])
                 : "l"(p));
}

// Backward-extend all set components of (v == x) against row i.
__device__ __forceinline__ void extend4(const int4 v, const int x, const int i,
                                        const int j0, const int* xs, int& best,
                                        const bool use_mask) {
    #pragma unroll
    for (int c = 0; c < 4; c++) {
        const int e = (c == 0) ? v.x : (c == 1) ? v.y : (c == 2) ? v.z : v.w;
        if (e == x && (!use_mask || (j0 + c < i))) {
            const int j = j0 + c;
            int L = 1, t = 1;
            while (t <= j && xs[i - t] == xs[j - t]) { ++L; ++t; }
            const int p = (L << 11) | j;
            if (p > best) best = p;
        }
    }
}

__global__ __launch_bounds__(256, 8)
void rosa_fused_kernel(const int* __restrict__ idx,
                       const float* __restrict__ emb,
                       float* __restrict__ out) {
    __shared__ int xs[TT];

    const int b    = blockIdx.x >> 7;            // 128 CTAs per batch
    const int rb   = (blockIdx.x & 127) * 8;     // 8 low rows per CTA
    const int tid  = threadIdx.x;
    const int w    = tid >> 5;
    const int lane = tid & 31;
    const int iA   = rb + w;                     // in [0, 1024)
    const int iB   = iA + 1024;                  // in [1024, 2048)

    // ---- Fill smem token row (8 KB). ----
    const int4* g  = (const int4*)(idx + (size_t)b * TT);
    int4*       s4 = (int4*)xs;
    s4[tid]       = g[tid];
    s4[tid + 256] = g[tid + 256];
    __syncthreads();

    // ---- Early zero stores for both rows: drain overlaps compare phase. ----
    float* oA = out + ((size_t)b * TT + iA) * CC;
    float* oB = oA + (size_t)1024 * CC;
    #pragma unroll
    for (int k = 0; k < 3; k++) {
        stg_v8_zero(oA + (lane + 32 * k) * 8);
        stg_v8_zero(oB + (lane + 32 * k) * 8);
    }

    const int xA = xs[iA], xB = xs[iB];
    int bestA = 0, bestB = 0;                    // (L<<11)|j ; 0 == no match

    int base = 0;
    // Chunks fully below iA: test BOTH rows on one LDS, no masks.
    for (; base + 128 <= iA; base += 128) {
        const int j0 = base + lane * 4;
        const int4 v = s4[j0 >> 2];
        if ((v.x == xA) | (v.y == xA) | (v.z == xA) | (v.w == xA))
            extend4(v, xA, iA, j0, xs, bestA, false);
        if ((v.x == xB) | (v.y == xB) | (v.z == xB) | (v.w == xB))
            extend4(v, xB, iB, j0, xs, bestB, false);
    }
    // Straddle chunk for row A (masked); row B still unmasked (base+128 <= iB).
    if (base < iA) {
        const int j0 = base + lane * 4;
        const int4 v = s4[j0 >> 2];
        if ((v.x == xA) | (v.y == xA) | (v.z == xA) | (v.w == xA))
            extend4(v, xA, iA, j0, xs, bestA, true);
        if ((v.x == xB) | (v.y == xB) | (v.z == xB) | (v.w == xB))
            extend4(v, xB, iB, j0, xs, bestB, false);
        base += 128;
    }
    // Remaining full chunks for row B only.
    for (; base + 128 <= iB; base += 128) {
        const int j0 = base + lane * 4;
        const int4 v = s4[j0 >> 2];
        if ((v.x == xB) | (v.y == xB) | (v.z == xB) | (v.w == xB))
            extend4(v, xB, iB, j0, xs, bestB, false);
    }
    // Tail chunk for row B (masked). j0 <= 2044 here, LDS in-bounds.
    if (base < iB) {
        const int j0 = base + lane * 4;
        const int4 v = s4[j0 >> 2];
        if ((v.x == xB) | (v.y == xB) | (v.z == xB) | (v.w == xB))
            extend4(v, xB, iB, j0, xs, bestB, true);
    }

    // ---- Reduce + rare matched-row overwrite (zeros already in flight). ----
    #pragma unroll
    for (int o = 16; o; o >>= 1) {
        bestA = max(bestA, __shfl_xor_sync(0xffffffffu, bestA, o));
        bestB = max(bestB, __shfl_xor_sync(0xffffffffu, bestB, o));
    }

    #pragma unroll
    for (int r = 0; r < 2; r++) {
        const int bst = r ? bestB : bestA;
        if (bst >= (1 << 11)) {                  // rare: ~42 rows total
            int pidx = (bst & 2047) + 1;
            if (pidx > TT - 1) pidx = TT - 1;
            const int tok = xs[pidx];
            const float* erow = emb + (size_t)tok * CC;
            float* orow = r ? oB : oA;
            float rv[24];
            #pragma unroll
            for (int k = 0; k < 3; k++)
                ldg_v8(erow + (lane + 32 * k) * 8, rv + 8 * k);
            #pragma unroll
            for (int k = 0; k < 3; k++)
                stg_v8(orow + (lane + 32 * k) * 8, rv + 8 * k);
        }
    }
}

extern "C" void kernel_launch(void* const* d_in, const int* in_sizes, int n_in,
                              void* d_out, int out_size) {
    const int*   idx = (const int*)d_in[0];
    const float* emb = (const float*)d_in[1];
    float*       out = (float*)d_out;

    rosa_fused_kernel<<<BB * 128, 256>>>(idx, emb, out);
}

// round 12
// speedup vs baseline: 1.4837x; 1.1604x over previous
#include <cuda_runtime.h>

// rosa_emb_layer: B=8, T=2048, V=50257, C=768
// inputs: d_in[0] = idx (B,T) int32, d_in[1] = emb (V,C) float32
// output: (B,T,C) float32
//
// R12 = R1 skeleton (2048 CTAs x 8 warps, ONE row per warp -- proven best
// latency hiding; every multi-row variant lengthened the serial chain and
// lost) with two in-place improvements:
//  1. Prefix-only smem fill: CTA only loads xs[0..i_base+7] (halves the
//     16MB of idx refill traffic sharing the LTS cap with the 50MB stores).
//  2. Hot loop split: mask-free full-chunk region at 2x int4 per iteration
//     (2 LDS in flight, no bounds ISETPs, half the dependent iterations),
//     one masked tail chunk.
// (L<<11)|j integer max == argmax(L + j*1e-5) with larger-j tie-break.
// Matched rows (~42 in the whole problem) take the rare extend/gather path.

#define TT 2048
#define BB 8
#define CC 768
#define WPB 8

__device__ __forceinline__ void stg_v8(float* p, const float* r) {
    asm volatile("st.global.v8.f32 [%0], {%1,%2,%3,%4,%5,%6,%7,%8};"
                 :: "l"(p), "f"(r[0]), "f"(r[1]), "f"(r[2]), "f"(r[3]),
                    "f"(r[4]), "f"(r[5]), "f"(r[6]), "f"(r[7]) : "memory");
}

__device__ __forceinline__ void stg_v8_zero(float* p) {
    asm volatile("st.global.v8.f32 [%0], {%1,%1,%1,%1,%1,%1,%1,%1};"
                 :: "l"(p), "f"(0.0f) : "memory");
}

__device__ __forceinline__ void ldg_v8(const float* p, float* r) {
    asm volatile("ld.global.nc.v8.f32 {%0,%1,%2,%3,%4,%5,%6,%7}, [%8];"
                 : "=f"(r[0]), "=f"(r[1]), "=f"(r[2]), "=f"(r[3]),
                   "=f"(r[4]), "=f"(r[5]), "=f"(r[6]), "=f"(r[7])
                 : "l"(p));
}

// Backward-extend every matching component of v against row i (rare path).
__device__ __forceinline__ void extend4(const int4 v, const int x, const int i,
                                        const int j0, const int* xs, int& best) {
    #pragma unroll
    for (int c = 0; c < 4; c++) {
        const int e = (c == 0) ? v.x : (c == 1) ? v.y : (c == 2) ? v.z : v.w;
        if (e == x) {
            const int j = j0 + c;
            int L = 1, t = 1;
            while (t <= j && xs[i - t] == xs[j - t]) { ++L; ++t; }
            const int p = (L << 11) | j;
            if (p > best) best = p;
        }
    }
}

__global__ __launch_bounds__(256, 8)
void rosa_emb_kernel(const int* __restrict__ idx,
                     const float* __restrict__ emb,
                     float* __restrict__ out) {
    __shared__ int xs[TT];

    const int cta_per_b = TT / WPB;               // 256
    const int b      = blockIdx.x / cta_per_b;
    const int i_base = (blockIdx.x % cta_per_b) * WPB;
    const int tid  = threadIdx.x;
    const int w    = tid >> 5;
    const int lane = tid & 31;
    const int i    = i_base + w;

    // ---- Prefix-only fill: this CTA needs xs[0 .. i_base+7]. ----
    const int4* g     = (const int4*)(idx + (size_t)b * TT);
    int4*       s4    = (int4*)xs;
    const int   nfill = (i_base >> 2) + 2;        // int4 count covering prefix
    for (int k = tid; k < nfill; k += 256) s4[k] = g[k];
    __syncthreads();

    const int xi = xs[i];
    int best = 0;              // (L<<11)|j ; 0 == no match

    // ---- Full-chunk region: chunks wholly < i, no bounds masks. ----
    const int ifull = i & ~127;                   // tail chunk start
    int base = 0;
    for (; base + 256 <= ifull; base += 256) {    // 2 chunks per iteration
        const int j0 = base + lane * 4;
        const int4 v0 = s4[j0 >> 2];
        const int4 v1 = s4[(j0 + 128) >> 2];
        const bool h0 = (v0.x == xi) | (v0.y == xi) | (v0.z == xi) | (v0.w == xi);
        const bool h1 = (v1.x == xi) | (v1.y == xi) | (v1.z == xi) | (v1.w == xi);
        if (h0 | h1) {                            // rare
            if (h0) extend4(v0, xi, i, j0,       xs, best);
            if (h1) extend4(v1, xi, i, j0 + 128, xs, best);
        }
    }
    if (base < ifull) {                           // one leftover full chunk
        const int j0 = base + lane * 4;
        const int4 v = s4[j0 >> 2];
        if ((v.x == xi) | (v.y == xi) | (v.z == xi) | (v.w == xi))
            extend4(v, xi, i, j0, xs, best);
        base += 128;
    }
    // ---- Masked tail chunk [ifull, i). ----
    if (base < i) {
        const int j0 = base + lane * 4;
        if (j0 < i) {
            const int4 v = s4[j0 >> 2];
            const bool m0 = (v.x == xi);
            const bool m1 = (v.y == xi) & (j0 + 1 < i);
            const bool m2 = (v.z == xi) & (j0 + 2 < i);
            const bool m3 = (v.w == xi) & (j0 + 3 < i);
            if (m0 | m1 | m2 | m3) {
                #pragma unroll
                for (int c = 0; c < 4; c++) {
                    const bool m = (c == 0) ? m0 : (c == 1) ? m1 : (c == 2) ? m2 : m3;
                    if (m) {
                        const int j = j0 + c;
                        int L = 1, t = 1;
                        while (t <= j && xs[i - t] == xs[j - t]) { ++L; ++t; }
                        const int p = (L << 11) | j;
                        if (p > best) best = p;
                    }
                }
            }
        }
    }

    // ---- Warp max-reduce the packed (L, j) score. ----
    #pragma unroll
    for (int o = 16; o; o >>= 1)
        best = max(best, __shfl_xor_sync(0xffffffffu, best, o));

    // ---- Epilogue: write this row (zeros, or emb[x[j*+1]]). ----
    float* orow = out + ((size_t)b * TT + i) * CC;
    if (best < (1 << 11)) {
        #pragma unroll
        for (int k = 0; k < 3; k++)
            stg_v8_zero(orow + (lane + 32 * k) * 8);
    } else {
        int pidx = (best & 2047) + 1;
        if (pidx > TT - 1) pidx = TT - 1;
        const int tok = xs[pidx];
        const float* erow = emb + (size_t)tok * CC;
        float rv[24];
        #pragma unroll
        for (int k = 0; k < 3; k++)
            ldg_v8(erow + (lane + 32 * k) * 8, rv + 8 * k);
        #pragma unroll
        for (int k = 0; k < 3; k++)
            stg_v8(orow + (lane + 32 * k) * 8, rv + 8 * k);
    }
}

extern "C" void kernel_launch(void* const* d_in, const int* in_sizes, int n_in,
                              void* d_out, int out_size) {
    const int*   idx = (const int*)d_in[0];
    const float* emb = (const float*)d_in[1];
    float*       out = (float*)d_out;

    rosa_emb_kernel<<<BB * (TT / WPB), 256>>>(idx, emb, out);
}